// round 2
// baseline (speedup 1.0000x reference)
#include <cuda_runtime.h>
#include <cuda_bf16.h>
#include <cstddef>

// Fixed problem shape: NX=432, NY=496, C=64, B=4 (P from in_sizes).
#define NXc 432
#define NYc 496
#define Cc  64
#define Bc  4
#define NQ  (NXc / 4)          // 108 float4 slots per row
#define NTHREADS (NQ * 4)      // 432: (xg in [0,108)) x (ch in [0,4))

// Inverse index grid: idx[b][y][x] = pillar id or -1. ~3.4 MB device global.
__device__ int g_idx[Bc * NYc * NXc];
__device__ int g_is64;

// Init grid to -1 (vectorized) and run the coord-dtype detection in one kernel.
// int64 little-endian small nonneg coords => odd int32 words all zero.
__global__ void init_idx_kernel(const int* __restrict__ coords) {
    int i = blockIdx.x * blockDim.x + threadIdx.x;
    if (i < Bc * NYc * NXc / 4) {
        ((int4*)g_idx)[i] = make_int4(-1, -1, -1, -1);
    }
    if (i == 0) {
        int is64 = 1;
        #pragma unroll 8
        for (int j = 0; j < 64; j++) {
            if (coords[2 * j + 1] != 0) { is64 = 0; break; }
        }
        g_is64 = is64;
    }
}

__global__ void scatter_idx_kernel(const int* __restrict__ coords, int P) {
    int p = blockIdx.x * blockDim.x + threadIdx.x;
    if (p >= P) return;
    int x, y, b;
    if (g_is64) {
        const long long* c64 = (const long long*)coords;
        x = (int)c64[3 * p + 0];
        y = (int)c64[3 * p + 1];
        b = (int)c64[3 * p + 2];
    } else {
        x = coords[3 * p + 0];
        y = coords[3 * p + 1];
        b = coords[3 * p + 2];
    }
    g_idx[(b * NYc + y) * NXc + x] = p;
}

// Output-centric scatter: one CTA per (b, y) row. Thread (xg, ch) owns the
// float4 of x-cells [4xg, 4xg+4) for channels [16ch, 16ch+16). It reads its 4
// pillar ids once (int4 from a 1.7KB SMEM row), then per 4-channel chunk does
// up to 4 predicated LDG.128 gathers (most threads: zero) and 4 coalesced
// STG.128 plane stores. No SMEM transpose -> L1 traffic ~= global traffic.
__global__ __launch_bounds__(NTHREADS)
void scatter_write_kernel(const float* __restrict__ feat, float* __restrict__ out) {
    __shared__ int sidx[NXc];

    const int y   = blockIdx.x;    // 0..495
    const int b   = blockIdx.y;    // 0..3
    const int tid = threadIdx.x;

    sidx[tid < NXc ? tid : 0] = g_idx[(b * NYc + y) * NXc + (tid < NXc ? tid : 0)];
    __syncthreads();

    const int xg = tid % NQ;       // 0..107
    const int ch = tid / NQ;       // 0..3  -> channels [16ch, 16ch+16)

    const int4 p4 = ((const int4*)sidx)[xg];

    const float* fp0 = feat + (size_t)p4.x * Cc;
    const float* fp1 = feat + (size_t)p4.y * Cc;
    const float* fp2 = feat + (size_t)p4.z * Cc;
    const float* fp3 = feat + (size_t)p4.w * Cc;

    const int c_base = ch * 16;
    // out element offset of (b, c_base, y, 4*xg)
    size_t obase = (((size_t)(b * Cc + c_base)) * NYc + y) * (size_t)NXc + 4 * xg;
    const size_t plane = (size_t)NYc * NXc;

    #pragma unroll
    for (int chunk = 0; chunk < 4; chunk++) {
        const int c0 = c_base + chunk * 4;
        float4 fa = make_float4(0.f, 0.f, 0.f, 0.f);
        float4 fb = fa, fc = fa, fd = fa;
        if (p4.x >= 0) fa = *(const float4*)(fp0 + c0);
        if (p4.y >= 0) fb = *(const float4*)(fp1 + c0);
        if (p4.z >= 0) fc = *(const float4*)(fp2 + c0);
        if (p4.w >= 0) fd = *(const float4*)(fp3 + c0);

        float4 v;
        v = make_float4(fa.x, fb.x, fc.x, fd.x);
        *(float4*)(out + obase + (size_t)(chunk * 4 + 0) * plane) = v;
        v = make_float4(fa.y, fb.y, fc.y, fd.y);
        *(float4*)(out + obase + (size_t)(chunk * 4 + 1) * plane) = v;
        v = make_float4(fa.z, fb.z, fc.z, fd.z);
        *(float4*)(out + obase + (size_t)(chunk * 4 + 2) * plane) = v;
        v = make_float4(fa.w, fb.w, fc.w, fd.w);
        *(float4*)(out + obase + (size_t)(chunk * 4 + 3) * plane) = v;
    }
}

extern "C" void kernel_launch(void* const* d_in, const int* in_sizes, int n_in,
                              void* d_out, int out_size) {
    const float* feat   = (const float*)d_in[0];   // [P, 64] fp32
    const int*   coords = (const int*)d_in[1];     // [P, 3] int32 or int64
    float*       out    = (float*)d_out;           // [B, 64, NY, NX] fp32

    const int P = in_sizes[0] / Cc;

    const int nvec = Bc * NYc * NXc / 4;
    init_idx_kernel<<<(nvec + 255) / 256, 256>>>(coords);

    scatter_idx_kernel<<<(P + 255) / 256, 256>>>(coords, P);

    dim3 grid(NYc, Bc);            // (496, 4) = 1984 CTAs
    scatter_write_kernel<<<grid, NTHREADS>>>(feat, out);
}